// round 17
// baseline (speedup 1.0000x reference)
#include <cuda_runtime.h>
#include <cuda_bf16.h>
#include <mma.h>
#include <math.h>
#include <stdint.h>

using namespace nvcuda;

// Problem constants
#define C_    192      // channels
#define NTOK  196      // tokens per stream
#define B_    256      // batch
#define L2N   392      // 2N
#define PHI_STRIDE (L2N * C_)   // 75264 floats per batch

// ---------------- scratch (device globals; no allocation) ----------------
__device__ float g_phi[(size_t)B_ * L2N * C_];   // [B][392][192]  (~77 MB)
__device__ __align__(16) __nv_bfloat16 g_Wbh1[C_ * C_];  // bf16 hi of folded w1 [o][i]
__device__ __align__(16) __nv_bfloat16 g_Wbl1[C_ * C_];  // bf16 lo residual
__device__ __align__(16) __nv_bfloat16 g_Wbh2[C_ * C_];
__device__ __align__(16) __nv_bfloat16 g_Wbl2[C_ * C_];
__device__ float g_bf1[C_];
__device__ float g_bf2[C_];
__device__ float g_u3[C_];
__device__ float g_u4s[L2N];
__device__ float g_u4s_part[56][L2N];
__device__ float g_c0_s;
__device__ float g_W[(size_t)B_ * L2N];          // W[b, l]

// ---------------- mega precompute: folds + u4s_part + c0 in ONE launch ----------------
// blocks 0..144: fold stream 1; 145..289: fold stream 2; 290..345: u4s_part; 346: c0
__global__ void mega_prep(const float* __restrict__ w1, const float* __restrict__ b1,
                          const float* __restrict__ g1, const float* __restrict__ be1,
                          const float* __restrict__ m1, const float* __restrict__ v1,
                          const float* __restrict__ w2, const float* __restrict__ b2,
                          const float* __restrict__ g2, const float* __restrict__ be2,
                          const float* __restrict__ m2, const float* __restrict__ v2,
                          const float* __restrict__ w4, const float* __restrict__ w5,
                          const float* __restrict__ b3, const float* __restrict__ b4,
                          const float* __restrict__ b5)
{
    const int blk = blockIdx.x, tid = threadIdx.x;
    if (blk < 290) {
        const int s = (blk >= 145) ? 1 : 0;
        const float* w  = s ? w2  : w1;
        const float* b  = s ? b2  : b1;
        const float* g  = s ? g2  : g1;
        const float* be = s ? be2 : be1;
        const float* m  = s ? m2  : m1;
        const float* v  = s ? v2  : v1;
        __nv_bfloat16* Wbh = s ? g_Wbh2 : g_Wbh1;
        __nv_bfloat16* Wbl = s ? g_Wbl2 : g_Wbl1;
        float* bf = s ? g_bf2 : g_bf1;
        int base = (blk - (s ? 145 : 0)) * 256 + tid;
        if (base < C_ * C_) {
            int o = base / C_;
            float inv = g[o] / sqrtf(v[o] + 1e-5f);
            float wf = w[base] * inv;
            __nv_bfloat16 hi = __float2bfloat16(wf);
            Wbh[base] = hi;
            Wbl[base] = __float2bfloat16(wf - __bfloat162float(hi));
        }
        if ((blk == 0 || blk == 145) && tid < C_) {
            int o = tid;
            float inv = g[o] / sqrtf(v[o] + 1e-5f);
            bf[o] = (b[o] - m[o]) * inv + be[o];
        }
    } else if (blk < 346) {
        const int j = blk - 290;                 // 0..55, owns o in [j*14, j*14+14)
        for (int mI = tid; mI < L2N; mI += 256) {
            float acc = 0.f;
            #pragma unroll
            for (int oo = 0; oo < 14; ++oo) {
                int o = j * 14 + oo;
                float ws = w5[C_ + o];
                acc += ws * (w4[o * 784 + mI] + w4[o * 784 + mI + L2N]);
            }
            g_u4s_part[j][mI] = acc;
        }
    } else {
        __shared__ float red[256];
        float p = 0.f;
        for (int t = tid; t < C_ + 784; t += 256)
            p += w5[t] * (t < C_ ? b3[t] : b4[t - C_]);
        red[tid] = p;
        __syncthreads();
        for (int s2 = 128; s2 > 0; s2 >>= 1) {
            if (tid < s2) red[tid] += red[tid + s2];
            __syncthreads();
        }
        if (tid == 0) g_c0_s = red[0] + b5[0];
    }
}

__global__ void u4s_reduce_kernel()
{
    const int m = threadIdx.x;
    float acc = 0.f;
    #pragma unroll
    for (int j = 0; j < 56; ++j) acc += g_u4s_part[j][m];
    g_u4s[m] = acc;
}

// u3[i] = sum_o w5[o] * w3[o*C+i]
__global__ void u3_kernel(const float* __restrict__ w5, const float* __restrict__ w3)
{
    __shared__ float part[576];
    int tid = threadIdx.x;
    int i = tid % C_;
    int h = tid / C_;
    float acc = 0.f;
    for (int o = h * 64; o < h * 64 + 64; ++o)
        acc += w5[o] * w3[o * C_ + i];
    part[tid] = acc;
    __syncthreads();
    if (tid < C_) g_u3[tid] = part[tid] + part[tid + C_] + part[tid + 2 * C_];
}

// ---------------- phi GEMM via wmma HMMA (bf16 split, fp32 accum) ----------------
// phi = relu(Ah*Wh + Ah*Wl + Al*Wh + bias).
// Block: 256 rows x 96 cols, 8 warps; warp = 32 rows (2 m-tiles) x 6 n-tiles.
// j-outer / mt-inner MMA loop: each B fragment pair feeds 6 MMAs (was 3) —
// halves the redundant cross-warp B smem traffic that made round-15 L1-bound.
// SMEM (dynamic, bytes):
//   B_HI @0      : 96 x 200 bf16 = 38400
//   B_LO @38400  : 38400
//   A_HI @76800  : 256 x 24 bf16 = 12288
//   A_LO @89088  : 12288            -> total 101376
//   C overlay @0 : 8 warps x 16 x 104 f32 = 53248 (after mma loop, over B region)
#define SM_B_HI 0
#define SM_B_LO 38400
#define SM_A_HI 76800
#define SM_A_LO 89088
#define SMEM_MMA 101376
#define BLDM 200
#define ALDM 24
#define CLDM 104

__global__ void __launch_bounds__(256, 1) gemm_phi_mma(const float* __restrict__ x,
                                                       const float* __restrict__ y)
{
    extern __shared__ char smem[];
    const int stream = blockIdx.z;
    const int half   = blockIdx.y;
    const int row0   = blockIdx.x * 256;
    const float* __restrict__ A = stream ? y : x;
    const __nv_bfloat16* __restrict__ Bh = stream ? g_Wbh2 : g_Wbh1;
    const __nv_bfloat16* __restrict__ Bl = stream ? g_Wbl2 : g_Wbl1;
    const float* __restrict__ bias = stream ? g_bf2 : g_bf1;
    const int moff = stream ? NTOK : 0;

    const int tid = threadIdx.x, warp = tid >> 5, lane = tid & 31;

    __nv_bfloat16* Bh_s = reinterpret_cast<__nv_bfloat16*>(smem + SM_B_HI);
    __nv_bfloat16* Bl_s = reinterpret_cast<__nv_bfloat16*>(smem + SM_B_LO);
    __nv_bfloat16* Ah_s = reinterpret_cast<__nv_bfloat16*>(smem + SM_A_HI);
    __nv_bfloat16* Al_s = reinterpret_cast<__nv_bfloat16*>(smem + SM_A_LO);

    // stage B (hi+lo): rows o in [half*96, half*96+96), all 192 i; ldm BLDM
    for (int i = tid; i < 96 * 24; i += 256) {
        int row = i / 24, q = i % 24;
        const uint4* srch = reinterpret_cast<const uint4*>(Bh + (size_t)(half * 96 + row) * C_ + q * 8);
        const uint4* srcl = reinterpret_cast<const uint4*>(Bl + (size_t)(half * 96 + row) * C_ + q * 8);
        *reinterpret_cast<uint4*>(Bh_s + row * BLDM + q * 8) = *srch;
        *reinterpret_cast<uint4*>(Bl_s + row * BLDM + q * 8) = *srcl;
    }

    wmma::fragment<wmma::accumulator, 16, 16, 16, float> acc[2][6];
    #pragma unroll
    for (int mt = 0; mt < 2; ++mt)
        #pragma unroll
        for (int j = 0; j < 6; ++j) wmma::fill_fragment(acc[mt][j], 0.f);
    __syncthreads();

    #pragma unroll 1
    for (int kc = 0; kc < 12; ++kc) {
        // stage A chunk: 256 rows x 16 cols fp32 -> bf16 hi/lo
        #pragma unroll
        for (int h2 = 0; h2 < 4; ++h2) {
            int f = tid + 256 * h2;          // 0..1023
            int row = f >> 2, q = f & 3;
            float4 v = *reinterpret_cast<const float4*>(
                A + (size_t)(row0 + row) * C_ + kc * 16 + q * 4);
            __nv_bfloat162 h01 = __floats2bfloat162_rn(v.x, v.y);
            __nv_bfloat162 h23 = __floats2bfloat162_rn(v.z, v.w);
            float2 f01 = __bfloat1622float2(h01);
            float2 f23 = __bfloat1622float2(h23);
            __nv_bfloat162 l01 = __floats2bfloat162_rn(v.x - f01.x, v.y - f01.y);
            __nv_bfloat162 l23 = __floats2bfloat162_rn(v.z - f23.x, v.w - f23.y);
            uint2 uh, ul;
            uh.x = *reinterpret_cast<uint32_t*>(&h01);
            uh.y = *reinterpret_cast<uint32_t*>(&h23);
            ul.x = *reinterpret_cast<uint32_t*>(&l01);
            ul.y = *reinterpret_cast<uint32_t*>(&l23);
            *reinterpret_cast<uint2*>(Ah_s + row * ALDM + q * 4) = uh;
            *reinterpret_cast<uint2*>(Al_s + row * ALDM + q * 4) = ul;
        }
        __syncthreads();

        wmma::fragment<wmma::matrix_a, 16, 16, 16, __nv_bfloat16, wmma::row_major> a_h[2], a_l[2];
        #pragma unroll
        for (int mt = 0; mt < 2; ++mt) {
            wmma::load_matrix_sync(a_h[mt], Ah_s + (warp * 32 + mt * 16) * ALDM, ALDM);
            wmma::load_matrix_sync(a_l[mt], Al_s + (warp * 32 + mt * 16) * ALDM, ALDM);
        }

        #pragma unroll
        for (int j = 0; j < 6; ++j) {
            wmma::fragment<wmma::matrix_b, 16, 16, 16, __nv_bfloat16, wmma::col_major> b_h, b_l;
            wmma::load_matrix_sync(b_h, Bh_s + j * 16 * BLDM + kc * 16, BLDM);
            wmma::load_matrix_sync(b_l, Bl_s + j * 16 * BLDM + kc * 16, BLDM);
            #pragma unroll
            for (int mt = 0; mt < 2; ++mt) {
                wmma::mma_sync(acc[mt][j], a_h[mt], b_h, acc[mt][j]);
                wmma::mma_sync(acc[mt][j], a_h[mt], b_l, acc[mt][j]);
                wmma::mma_sync(acc[mt][j], a_l[mt], b_h, acc[mt][j]);
            }
        }
        __syncthreads();   // A buffers reused next chunk
    }

    // epilogue: per m-tile, park acc in smem (overlaying retired B region),
    // then bias+relu+float4 scatter. Same-warp write/read — no block sync needed.
    float* Cw = reinterpret_cast<float*>(smem) + warp * (16 * CLDM);
    #pragma unroll
    for (int mt = 0; mt < 2; ++mt) {
        #pragma unroll
        for (int j = 0; j < 6; ++j)
            wmma::store_matrix_sync(Cw + 16 * j, acc[mt][j], CLDM, wmma::mem_row_major);

        #pragma unroll
        for (int it = 0; it < 12; ++it) {
            int idx = lane + 32 * it;            // 0..383 = 16 rows x 24 quads
            int r = idx / 24, q = idx % 24;
            int row = row0 + warp * 32 + mt * 16 + r;
            int bI  = row / NTOK;
            int n   = row - bI * NTOK;
            int c   = half * 96 + q * 4;
            float4 v = *reinterpret_cast<const float4*>(Cw + r * CLDM + q * 4);
            float4 bv = *reinterpret_cast<const float4*>(bias + c);
            float4 o;
            o.x = fmaxf(v.x + bv.x, 0.f);
            o.y = fmaxf(v.y + bv.y, 0.f);
            o.z = fmaxf(v.z + bv.z, 0.f);
            o.w = fmaxf(v.w + bv.w, 0.f);
            *reinterpret_cast<float4*>(g_phi + ((size_t)bI * L2N + moff + n) * C_ + c) = o;
        }
    }
}

// ---------------- fused s + W kernel: 2 blocks per batch, 512 threads ----------------
__global__ void __launch_bounds__(512) sw_kernel()
{
    const int b    = blockIdx.y;
    const int half = blockIdx.x;
    __shared__ float u4s_s[L2N];
    __shared__ float part[384];
    __shared__ float coef[C_];

    const int tid = threadIdx.x;
    for (int i = tid; i < L2N; i += 512) u4s_s[i] = g_u4s[i];
    __syncthreads();

    const float* __restrict__ pb = g_phi + (size_t)b * PHI_STRIDE;

    if (tid < 384) {
        const int c = tid % C_;
        const int h = tid / C_;
        const int m0 = h * NTOK;
        float acc = 0.f;
        #pragma unroll 4
        for (int m = 0; m < NTOK; ++m)
            acc += u4s_s[m0 + m] * pb[(size_t)(m0 + m) * C_ + c];
        part[tid] = acc;
    }
    __syncthreads();
    if (tid < C_) coef[tid] = g_u3[tid] + part[tid] + part[tid + C_];
    __syncthreads();

    const int warp = tid >> 5, lane = tid & 31;
    const int lbase = half * NTOK;
    const float cc0 = g_c0_s;
    for (int lo = warp; lo < NTOK; lo += 16) {
        const int l = lbase + lo;
        const float* row = pb + (size_t)l * C_;
        float p = 0.f;
        #pragma unroll
        for (int j = 0; j < 6; ++j) {
            int c = lane + 32 * j;
            p += coef[c] * row[c];
        }
        #pragma unroll
        for (int off = 16; off > 0; off >>= 1)
            p += __shfl_xor_sync(0xffffffffu, p, off);
        if (lane == 0) g_W[(size_t)b * L2N + l] = p + cc0;
    }
}

// ---------------- output: out[b,c,n] = x[b,n,c]*W[b,n] + y[b,n,c]*W[b,n+196] ----------------
__global__ void out_kernel(const float* __restrict__ x, const float* __restrict__ y,
                           float* __restrict__ out)
{
    const int b  = blockIdx.z;
    const int c0 = blockIdx.y * 32;
    const int n0 = blockIdx.x * 32;
    __shared__ float xs[32][33], ys[32][33];
    const int tx = threadIdx.x, ty = threadIdx.y;

    int n = n0 + ty;
    if (n < NTOK) {
        size_t src = ((size_t)b * NTOK + n) * C_ + c0 + tx;
        xs[ty][tx] = x[src];
        ys[ty][tx] = y[src];
    }
    __syncthreads();

    int nn = n0 + tx;
    if (nn < NTOK) {
        float wl = g_W[(size_t)b * L2N + nn];
        float wr = g_W[(size_t)b * L2N + NTOK + nn];
        out[((size_t)b * C_ + c0 + ty) * NTOK + nn] = xs[tx][ty] * wl + ys[tx][ty] * wr;
    }
}

// ---------------- launch ----------------
extern "C" void kernel_launch(void* const* d_in, const int* in_sizes, int n_in,
                              void* d_out, int out_size)
{
    const float* x   = (const float*)d_in[0];
    const float* y   = (const float*)d_in[1];
    const float* w1  = (const float*)d_in[2];
    const float* b1  = (const float*)d_in[3];
    const float* g1  = (const float*)d_in[4];
    const float* be1 = (const float*)d_in[5];
    const float* m1  = (const float*)d_in[6];
    const float* v1  = (const float*)d_in[7];
    const float* w2  = (const float*)d_in[8];
    const float* b2  = (const float*)d_in[9];
    const float* g2  = (const float*)d_in[10];
    const float* be2 = (const float*)d_in[11];
    const float* m2  = (const float*)d_in[12];
    const float* v2  = (const float*)d_in[13];
    const float* w3  = (const float*)d_in[14];
    const float* b3  = (const float*)d_in[15];
    const float* w4  = (const float*)d_in[16];
    const float* b4  = (const float*)d_in[17];
    const float* w5  = (const float*)d_in[18];
    const float* b5  = (const float*)d_in[19];
    float* out = (float*)d_out;

    cudaFuncSetAttribute(gemm_phi_mma, cudaFuncAttributeMaxDynamicSharedMemorySize, SMEM_MMA);

    // gemm must stay the 4th launch (ncu capture slot)
    mega_prep<<<347, 256>>>(w1, b1, g1, be1, m1, v1,
                            w2, b2, g2, be2, m2, v2,
                            w4, w5, b3, b4, b5);
    u4s_reduce_kernel<<<1, L2N>>>();
    u3_kernel<<<1, 576>>>(w5, w3);
    gemm_phi_mma<<<dim3(196, 2, 2), 256, SMEM_MMA>>>(x, y);
    sw_kernel<<<dim3(2, B_), 512>>>();
    out_kernel<<<dim3(7, 6, B_), dim3(32, 32)>>>(x, y, out);
}